// round 1
// baseline (speedup 1.0000x reference)
#include <cuda_runtime.h>
#include <cuda_bf16.h>

// Problem constants
#define BATCH 2
#define SEQ   2048
#define DMODEL 1024
#define NHEAD 16
#define DHEAD 64
#define MAXLEN 2048

// ---------------------------------------------------------------------------
// Scratch for q,k,v in (b,h,s,d) layout: [B*H][S][DHEAD]
// ---------------------------------------------------------------------------
__device__ float g_q[BATCH * NHEAD * SEQ * DHEAD];
__device__ float g_k[BATCH * NHEAD * SEQ * DHEAD];
__device__ float g_v[BATCH * NHEAD * SEQ * DHEAD];

// ---------------------------------------------------------------------------
// QKV projection: Y = x @ W + b   for W in {Wq,Wk,Wv} selected by blockIdx.z.
// M = B*S = 4096, K = 1024, N = 1024. 128x128x16 tiles, 256 threads, 8x8.
// Output scattered into (b,h,s,d) layout.
// ---------------------------------------------------------------------------
#define GM 128
#define GN 128
#define GK 16

__global__ __launch_bounds__(256) void qkv_gemm_kernel(
    const float* __restrict__ x,
    const float* __restrict__ W0, const float* __restrict__ b0,
    const float* __restrict__ W1, const float* __restrict__ b1,
    const float* __restrict__ W2, const float* __restrict__ b2)
{
    __shared__ float As[GK][GM];
    __shared__ float Bs[GK][GN];

    const int z = blockIdx.z;
    const float* W    = (z == 0) ? W0 : (z == 1) ? W1 : W2;
    const float* bias = (z == 0) ? b0 : (z == 1) ? b1 : b2;
    float* outp       = (z == 0) ? g_q : (z == 1) ? g_k : g_v;

    const int m0 = blockIdx.y * GM;
    const int n0 = blockIdx.x * GN;
    const int tid = threadIdx.x;
    const int tx = tid & 15;
    const int ty = tid >> 4;

    float acc[8][8];
    #pragma unroll
    for (int i = 0; i < 8; i++)
        #pragma unroll
        for (int j = 0; j < 8; j++) acc[i][j] = 0.f;

    for (int kt = 0; kt < DMODEL; kt += GK) {
        // A tile: 128 rows x 16 k  (512 float4)
        #pragma unroll
        for (int u = 0; u < 2; u++) {
            int f = tid + u * 256;
            int row = f >> 2;
            int kc  = (f & 3) * 4;
            float4 a = *(const float4*)&x[(size_t)(m0 + row) * DMODEL + kt + kc];
            As[kc + 0][row] = a.x;
            As[kc + 1][row] = a.y;
            As[kc + 2][row] = a.z;
            As[kc + 3][row] = a.w;
        }
        // B tile: 16 k x 128 cols (512 float4)
        #pragma unroll
        for (int u = 0; u < 2; u++) {
            int f = tid + u * 256;
            int kr = f >> 5;
            int nc = (f & 31) * 4;
            *(float4*)&Bs[kr][nc] =
                *(const float4*)&W[(size_t)(kt + kr) * DMODEL + n0 + nc];
        }
        __syncthreads();

        #pragma unroll
        for (int kk = 0; kk < GK; kk++) {
            float a[8], bb[8];
            *(float4*)&a[0]  = *(float4*)&As[kk][ty * 8];
            *(float4*)&a[4]  = *(float4*)&As[kk][ty * 8 + 4];
            *(float4*)&bb[0] = *(float4*)&Bs[kk][tx * 8];
            *(float4*)&bb[4] = *(float4*)&Bs[kk][tx * 8 + 4];
            #pragma unroll
            for (int i = 0; i < 8; i++)
                #pragma unroll
                for (int j = 0; j < 8; j++)
                    acc[i][j] += a[i] * bb[j];
        }
        __syncthreads();
    }

    // Epilogue: scatter into (b,h,s,d)
    #pragma unroll
    for (int i = 0; i < 8; i++) {
        int m = m0 + ty * 8 + i;
        int b = m >> 11;       // / SEQ
        int s = m & (SEQ - 1);
        #pragma unroll
        for (int j = 0; j < 8; j++) {
            int n = n0 + tx * 8 + j;
            int h = n >> 6;
            int d = n & 63;
            outp[(((size_t)(b * NHEAD + h)) * SEQ + s) * DHEAD + d] = acc[i][j] + bias[n];
        }
    }
}

// ---------------------------------------------------------------------------
// Relative-position causal flash attention.
//   logits[s,t] = (q_s.k_t + q_s.Er[S-1+t-s]) / 8   for t<=s, else -inf
// 128 query rows per block, 128 keys per iteration, 256 threads, 8x8 microtile.
// SMEM (dynamic, 160KB): q[128][64] | k[128][64] | v[128][64] | ep (union):
//   er band [256][64] during score phase, p [128][128] during PV phase.
// ---------------------------------------------------------------------------
#define AM 128
#define AN 128

__global__ __launch_bounds__(256, 1) void relattn_kernel(
    const float* __restrict__ Er, float* __restrict__ out)
{
    extern __shared__ float sm[];
    float* q_s = sm;                 // 8192 floats
    float* k_s = sm + 8192;          // 8192
    float* v_s = sm + 16384;         // 8192
    float* ep  = sm + 24576;         // 16384 (er band / p union)

    const int sb = blockIdx.x;          // 0..15
    const int bh = blockIdx.y;          // 0..31
    const int b  = bh >> 4;
    const int h  = bh & 15;
    const int s0 = sb * AM;

    const float* Q = g_q + (size_t)bh * SEQ * DHEAD;
    const float* K = g_k + (size_t)bh * SEQ * DHEAD;
    const float* V = g_v + (size_t)bh * SEQ * DHEAD;

    const int tid = threadIdx.x;
    const int tx = tid & 15;
    const int ty = tid >> 4;

    // Load q tile (2048 float4)
    {
        const float4* Q4 = (const float4*)(Q + (size_t)s0 * DHEAD);
        #pragma unroll
        for (int u = 0; u < 8; u++) {
            int f = tid + u * 256;
            ((float4*)q_s)[f] = Q4[f];
        }
    }

    float m_r[8], l_r[8];
    float o_acc[8][4];
    #pragma unroll
    for (int i = 0; i < 8; i++) {
        m_r[i] = -1e30f;
        l_r[i] = 0.f;
        #pragma unroll
        for (int c = 0; c < 4; c++) o_acc[i][c] = 0.f;
    }

    const float4* Er4 = (const float4*)Er;   // MAXLEN == SEQ, offset 0

    for (int t0 = 0; t0 <= s0; t0 += AN) {
        __syncthreads();   // prev iter's p/v reads done before overwrite

        // Load k, v tiles (2048 float4 each)
        {
            const float4* K4 = (const float4*)(K + (size_t)t0 * DHEAD);
            const float4* V4 = (const float4*)(V + (size_t)t0 * DHEAD);
            #pragma unroll
            for (int u = 0; u < 8; u++) {
                int f = tid + u * 256;
                ((float4*)k_s)[f] = K4[f];
                ((float4*)v_s)[f] = V4[f];
            }
        }
        // Load Er band: rows l0..l0+255 (4096 float4). band = (j - i) + 127
        {
            int l0 = t0 - s0 + (SEQ - 1) - 127;
            #pragma unroll
            for (int u = 0; u < 16; u++) {
                int f = tid + u * 256;
                int r = f >> 4;
                int gl = l0 + r;
                gl = gl < 0 ? 0 : (gl > SEQ - 1 ? SEQ - 1 : gl);
                ((float4*)ep)[f] = Er4[gl * 16 + (f & 15)];
            }
        }
        __syncthreads();

        float acc[8][8];
        #pragma unroll
        for (int i = 0; i < 8; i++)
            #pragma unroll
            for (int j = 0; j < 8; j++) acc[i][j] = 0.f;

        const bool fullmask = (t0 + tx * 8) > (s0 + ty * 8 + 7);
        if (!fullmask) {
            // ---- QK phase ----
            #pragma unroll 4
            for (int d4 = 0; d4 < 16; d4++) {
                float4 qv[8], kv[8];
                #pragma unroll
                for (int i = 0; i < 8; i++)
                    qv[i] = *(float4*)&q_s[(ty * 8 + i) * DHEAD + d4 * 4];
                #pragma unroll
                for (int j = 0; j < 8; j++)
                    kv[j] = *(float4*)&k_s[(tx * 8 + j) * DHEAD + d4 * 4];
                #pragma unroll
                for (int i = 0; i < 8; i++)
                    #pragma unroll
                    for (int j = 0; j < 8; j++)
                        acc[i][j] += qv[i].x * kv[j].x + qv[i].y * kv[j].y +
                                     qv[i].z * kv[j].z + qv[i].w * kv[j].w;
            }
            // ---- REL phase: acc[i][j] += q_i . er_band[(tx*8+j)-(ty*8+i)+127]
            #pragma unroll
            for (int i = 0; i < 8; i++) {
                int row = ty * 8 + i;
                int bb = tx * 8 - row + 127;   // band index for j=0, in [0,247]
                #pragma unroll 4
                for (int d4 = 0; d4 < 16; d4++) {
                    float4 qv = *(float4*)&q_s[row * DHEAD + d4 * 4];
                    #pragma unroll
                    for (int j = 0; j < 8; j++) {
                        float4 ev = *(float4*)&ep[(bb + j) * DHEAD + d4 * 4];
                        acc[i][j] += qv.x * ev.x + qv.y * ev.y +
                                     qv.z * ev.z + qv.w * ev.w;
                    }
                }
            }
        }

        // ---- mask + scale + row max (16-lane half-warp reduction) ----
        float pmax[8];
        #pragma unroll
        for (int i = 0; i < 8; i++) {
            int sg = s0 + ty * 8 + i;
            float mx = -1e30f;
            #pragma unroll
            for (int j = 0; j < 8; j++) {
                int tg = t0 + tx * 8 + j;
                float v = (fullmask || (tg > sg)) ? -1e30f : acc[i][j] * 0.125f;
                acc[i][j] = v;
                mx = fmaxf(mx, v);
            }
            #pragma unroll
            for (int off = 8; off > 0; off >>= 1)
                mx = fmaxf(mx, __shfl_xor_sync(0xffffffffu, mx, off));
            pmax[i] = mx;
        }

        __syncthreads();   // all er reads done before p overwrites ep

        // ---- online softmax update; write p ----
        #pragma unroll
        for (int i = 0; i < 8; i++) {
            float m_new = fmaxf(m_r[i], pmax[i]);
            float alpha = __expf(m_r[i] - m_new);
            float pj[8];
            float lsum = 0.f;
            #pragma unroll
            for (int j = 0; j < 8; j++) {
                float p = __expf(acc[i][j] - m_new);
                pj[j] = p;
                lsum += p;
            }
            #pragma unroll
            for (int off = 8; off > 0; off >>= 1)
                lsum += __shfl_xor_sync(0xffffffffu, lsum, off);
            l_r[i] = l_r[i] * alpha + lsum;
            m_r[i] = m_new;
            #pragma unroll
            for (int c = 0; c < 4; c++) o_acc[i][c] *= alpha;
            *(float4*)&ep[(ty * 8 + i) * AN + tx * 8]     = make_float4(pj[0], pj[1], pj[2], pj[3]);
            *(float4*)&ep[(ty * 8 + i) * AN + tx * 8 + 4] = make_float4(pj[4], pj[5], pj[6], pj[7]);
        }

        __syncthreads();

        // ---- PV: o[i][tx*4+c] += sum_j p[i][j] * v[j][tx*4+c] ----
        #pragma unroll 4
        for (int j4 = 0; j4 < 32; j4++) {
            float4 vv[4];
            #pragma unroll
            for (int jj = 0; jj < 4; jj++)
                vv[jj] = *(float4*)&v_s[(j4 * 4 + jj) * DHEAD + tx * 4];
            #pragma unroll
            for (int i = 0; i < 8; i++) {
                float4 pv = *(float4*)&ep[(ty * 8 + i) * AN + j4 * 4];
                o_acc[i][0] += pv.x * vv[0].x + pv.y * vv[1].x + pv.z * vv[2].x + pv.w * vv[3].x;
                o_acc[i][1] += pv.x * vv[0].y + pv.y * vv[1].y + pv.z * vv[2].y + pv.w * vv[3].y;
                o_acc[i][2] += pv.x * vv[0].z + pv.y * vv[1].z + pv.z * vv[2].z + pv.w * vv[3].z;
                o_acc[i][3] += pv.x * vv[0].w + pv.y * vv[1].w + pv.z * vv[2].w + pv.w * vv[3].w;
            }
        }
    }

    // ---- epilogue: out[b][s][h*64 + d] = o / l ----
    #pragma unroll
    for (int i = 0; i < 8; i++) {
        int sg = s0 + ty * 8 + i;
        float inv = 1.f / l_r[i];
        float4 r;
        r.x = o_acc[i][0] * inv;
        r.y = o_acc[i][1] * inv;
        r.z = o_acc[i][2] * inv;
        r.w = o_acc[i][3] * inv;
        *(float4*)&out[((size_t)b * SEQ + sg) * DMODEL + h * DHEAD + tx * 4] = r;
    }
}

// ---------------------------------------------------------------------------
extern "C" void kernel_launch(void* const* d_in, const int* in_sizes, int n_in,
                              void* d_out, int out_size)
{
    const float* x  = (const float*)d_in[0];
    const float* Wq = (const float*)d_in[1];
    const float* bq = (const float*)d_in[2];
    const float* Wk = (const float*)d_in[3];
    const float* bk = (const float*)d_in[4];
    const float* Wv = (const float*)d_in[5];
    const float* bv = (const float*)d_in[6];
    const float* Er = (const float*)d_in[7];
    float* out = (float*)d_out;

    (void)in_sizes; (void)n_in; (void)out_size;

    cudaFuncSetAttribute(relattn_kernel,
                         cudaFuncAttributeMaxDynamicSharedMemorySize, 160 * 1024);

    dim3 g1(DMODEL / GN, (BATCH * SEQ) / GM, 3);
    qkv_gemm_kernel<<<g1, 256>>>(x, Wq, bq, Wk, bk, Wv, bv);

    dim3 g2(SEQ / AM, BATCH * NHEAD);
    relattn_kernel<<<g2, 256, 160 * 1024>>>(Er, out);
}

// round 2
// speedup vs baseline: 4.4490x; 4.4490x over previous
#include <cuda_runtime.h>
#include <cuda_bf16.h>

// Problem constants
#define BATCH 2
#define SEQ   2048
#define DMODEL 1024
#define NHEAD 16
#define DHEAD 64

// ---------------------------------------------------------------------------
// Scratch for q,k,v in (b,h,s,d) layout: [B*H][S][DHEAD]
// ---------------------------------------------------------------------------
__device__ float g_q[BATCH * NHEAD * SEQ * DHEAD];
__device__ float g_k[BATCH * NHEAD * SEQ * DHEAD];
__device__ float g_v[BATCH * NHEAD * SEQ * DHEAD];

// ---------------------------------------------------------------------------
// QKV projection: Y = x @ W + b. M=4096, N=K=1024. 128x128x16 tiles, 256 thr.
// __launch_bounds__(256,2): 16KB smem + <=128 regs -> 2 CTAs/SM -> all 256
// CTAs resident in ONE wave.
// ---------------------------------------------------------------------------
#define GM 128
#define GN 128
#define GK 16

__global__ __launch_bounds__(256, 2) void qkv_gemm_kernel(
    const float* __restrict__ x,
    const float* __restrict__ W0, const float* __restrict__ b0,
    const float* __restrict__ W1, const float* __restrict__ b1,
    const float* __restrict__ W2, const float* __restrict__ b2)
{
    __shared__ float As[GK][GM];
    __shared__ float Bs[GK][GN];

    const int z = blockIdx.z;
    const float* W    = (z == 0) ? W0 : (z == 1) ? W1 : W2;
    const float* bias = (z == 0) ? b0 : (z == 1) ? b1 : b2;
    float* outp       = (z == 0) ? g_q : (z == 1) ? g_k : g_v;

    const int m0 = blockIdx.y * GM;
    const int n0 = blockIdx.x * GN;
    const int tid = threadIdx.x;
    const int tx = tid & 15;
    const int ty = tid >> 4;

    float acc[8][8];
    #pragma unroll
    for (int i = 0; i < 8; i++)
        #pragma unroll
        for (int j = 0; j < 8; j++) acc[i][j] = 0.f;

    for (int kt = 0; kt < DMODEL; kt += GK) {
        #pragma unroll
        for (int u = 0; u < 2; u++) {
            int f = tid + u * 256;
            int row = f >> 2;
            int kc  = (f & 3) * 4;
            float4 a = *(const float4*)&x[(size_t)(m0 + row) * DMODEL + kt + kc];
            As[kc + 0][row] = a.x;
            As[kc + 1][row] = a.y;
            As[kc + 2][row] = a.z;
            As[kc + 3][row] = a.w;
        }
        #pragma unroll
        for (int u = 0; u < 2; u++) {
            int f = tid + u * 256;
            int kr = f >> 5;
            int nc = (f & 31) * 4;
            *(float4*)&Bs[kr][nc] =
                *(const float4*)&W[(size_t)(kt + kr) * DMODEL + n0 + nc];
        }
        __syncthreads();

        #pragma unroll
        for (int kk = 0; kk < GK; kk++) {
            float a[8], bb[8];
            *(float4*)&a[0]  = *(float4*)&As[kk][ty * 8];
            *(float4*)&a[4]  = *(float4*)&As[kk][ty * 8 + 4];
            *(float4*)&bb[0] = *(float4*)&Bs[kk][tx * 8];
            *(float4*)&bb[4] = *(float4*)&Bs[kk][tx * 8 + 4];
            #pragma unroll
            for (int i = 0; i < 8; i++)
                #pragma unroll
                for (int j = 0; j < 8; j++)
                    acc[i][j] += a[i] * bb[j];
        }
        __syncthreads();
    }

    // Epilogue: scatter into (b,h,s,d). n base = n0+tx*8 is 8-aligned so the
    // 8 j-columns stay inside one head -> two float4 stores per row.
    const int n = n0 + tx * 8;
    const int h = n >> 6;
    const int d = n & 63;
    float4 bv0 = *(const float4*)&bias[n];
    float4 bv1 = *(const float4*)&bias[n + 4];
    #pragma unroll
    for (int i = 0; i < 8; i++) {
        int m = m0 + ty * 8 + i;
        int b = m >> 11;
        int s = m & (SEQ - 1);
        float* o = &outp[(((size_t)(b * NHEAD + h)) * SEQ + s) * DHEAD + d];
        float4 r0, r1;
        r0.x = acc[i][0] + bv0.x; r0.y = acc[i][1] + bv0.y;
        r0.z = acc[i][2] + bv0.z; r0.w = acc[i][3] + bv0.w;
        r1.x = acc[i][4] + bv1.x; r1.y = acc[i][5] + bv1.y;
        r1.z = acc[i][6] + bv1.z; r1.w = acc[i][7] + bv1.w;
        *(float4*)&o[0] = r0;
        *(float4*)&o[4] = r1;
    }
}

// ---------------------------------------------------------------------------
// Relative-position causal flash attention, conflict-free SMEM mapping.
// Interleaved thread tiles: thread (ty,tx) owns rows ty+16i, cols tx+16j.
// All SMEM tiles padded to AP=68 floats/row -> lane stride 68 words -> banks
// 4*tx..4*tx+3 per quarter phase -> conflict-free LDS.128.
// SMEM: q[128][68] | k[128][68] | v[128][68] | union{band[256][68], p[128][132]}
// ---------------------------------------------------------------------------
#define AM 128
#define AN 128
#define AP 68
#define PP 132

__global__ __launch_bounds__(256, 1) void relattn_kernel(
    const float* __restrict__ Er, float* __restrict__ out)
{
    extern __shared__ float sm[];
    float* q_s = sm;                    // 128*68 = 8704 floats
    float* k_s = sm + 8704;
    float* v_s = sm + 17408;
    float* ep  = sm + 26112;            // band 256*68=17408 / p 128*132=16896

    const int sb = (int)gridDim.x - 1 - (int)blockIdx.x;  // heavy blocks first
    const int bh = blockIdx.y;
    const int b  = bh >> 4;
    const int h  = bh & 15;
    const int s0 = sb * AM;

    const float* Q = g_q + (size_t)bh * SEQ * DHEAD;
    const float* K = g_k + (size_t)bh * SEQ * DHEAD;
    const float* V = g_v + (size_t)bh * SEQ * DHEAD;

    const int tid = threadIdx.x;
    const int tx = tid & 15;
    const int ty = tid >> 4;

    // Load q tile into padded layout
    {
        const float4* Q4 = (const float4*)(Q + (size_t)s0 * DHEAD);
        #pragma unroll
        for (int u = 0; u < 8; u++) {
            int f = tid + u * 256;
            int row = f >> 4;
            int c4  = f & 15;
            *(float4*)&q_s[row * AP + c4 * 4] = Q4[row * 16 + c4];
        }
    }

    float m_r[8], l_r[8];
    float o_acc[8][4];
    #pragma unroll
    for (int i = 0; i < 8; i++) {
        m_r[i] = -1e30f;
        l_r[i] = 0.f;
        #pragma unroll
        for (int c = 0; c < 4; c++) o_acc[i][c] = 0.f;
    }

    const float4* Er4 = (const float4*)Er;

    for (int t0 = 0; t0 <= s0; t0 += AN) {
        __syncthreads();   // prior p/v reads done before overwrite

        // k, v tiles
        {
            const float4* K4 = (const float4*)(K + (size_t)t0 * DHEAD);
            const float4* V4 = (const float4*)(V + (size_t)t0 * DHEAD);
            #pragma unroll
            for (int u = 0; u < 8; u++) {
                int f = tid + u * 256;
                int row = f >> 4;
                int c4  = f & 15;
                *(float4*)&k_s[row * AP + c4 * 4] = K4[row * 16 + c4];
                *(float4*)&v_s[row * AP + c4 * 4] = V4[row * 16 + c4];
            }
        }
        // Er band rows l0..l0+255; band row r <-> (t-s)-(t0-s0)+127
        {
            int l0 = t0 - s0 + (SEQ - 1) - 127;   // >= 0 always here
            #pragma unroll
            for (int u = 0; u < 16; u++) {
                int f = tid + u * 256;
                int r = f >> 4;
                int gl = l0 + r;
                gl = gl > SEQ - 1 ? SEQ - 1 : gl;   // clamp top (masked rows only)
                *(float4*)&ep[r * AP + (f & 15) * 4] = Er4[gl * 16 + (f & 15)];
            }
        }
        __syncthreads();

        float acc[8][8];
        #pragma unroll
        for (int i = 0; i < 8; i++)
            #pragma unroll
            for (int j = 0; j < 8; j++) acc[i][j] = 0.f;

        // ---- fused QK + REL, k-dim = d (16 steps of 4) ----
        const int bandrow0 = (tx - ty + 15) * AP;   // c=0 (j-i=-7)
        #pragma unroll 2
        for (int d4 = 0; d4 < 16; d4++) {
            float4 qv[8], kv[8];
            #pragma unroll
            for (int i = 0; i < 8; i++)
                qv[i] = *(float4*)&q_s[(ty + 16 * i) * AP + d4 * 4];
            #pragma unroll
            for (int j = 0; j < 8; j++)
                kv[j] = *(float4*)&k_s[(tx + 16 * j) * AP + d4 * 4];
            #pragma unroll
            for (int i = 0; i < 8; i++)
                #pragma unroll
                for (int j = 0; j < 8; j++)
                    acc[i][j] += qv[i].x * kv[j].x + qv[i].y * kv[j].y +
                                 qv[i].z * kv[j].z + qv[i].w * kv[j].w;
            // REL: acc[i][j] += q_i . band[tx-ty+16(j-i)+127]
            #pragma unroll
            for (int c = 0; c < 15; c++) {
                float4 ev = *(float4*)&ep[bandrow0 + c * (16 * AP) + d4 * 4];
                #pragma unroll
                for (int i = 0; i < 8; i++) {
                    int j = i + c - 7;
                    if (j >= 0 && j < 8)
                        acc[i][j] += qv[i].x * ev.x + qv[i].y * ev.y +
                                     qv[i].z * ev.z + qv[i].w * ev.w;
                }
            }
        }

        // ---- mask (diagonal tile only) + scale + row max ----
        const bool diag = (t0 == s0);
        float pmax[8];
        #pragma unroll
        for (int i = 0; i < 8; i++) {
            int sgl = ty + 16 * i;
            float mx = -1e30f;
            #pragma unroll
            for (int j = 0; j < 8; j++) {
                int tgl = tx + 16 * j;
                float v = acc[i][j] * 0.125f;
                if (diag && tgl > sgl) v = -1e30f;
                acc[i][j] = v;
                mx = fmaxf(mx, v);
            }
            #pragma unroll
            for (int off = 8; off > 0; off >>= 1)
                mx = fmaxf(mx, __shfl_xor_sync(0xffffffffu, mx, off));
            pmax[i] = mx;
        }

        __syncthreads();   // band reads done before p overwrites ep

        // ---- online softmax update; write p (conflict-free scalar STS) ----
        #pragma unroll
        for (int i = 0; i < 8; i++) {
            float m_new = fmaxf(m_r[i], pmax[i]);
            float alpha = __expf(m_r[i] - m_new);
            float lsum = 0.f;
            int rowoff = (ty + 16 * i) * PP + tx;
            #pragma unroll
            for (int j = 0; j < 8; j++) {
                float p = __expf(acc[i][j] - m_new);
                ep[rowoff + 16 * j] = p;
                lsum += p;
            }
            #pragma unroll
            for (int off = 8; off > 0; off >>= 1)
                lsum += __shfl_xor_sync(0xffffffffu, lsum, off);
            l_r[i] = l_r[i] * alpha + lsum;
            m_r[i] = m_new;
            #pragma unroll
            for (int c = 0; c < 4; c++) o_acc[i][c] *= alpha;
        }

        __syncthreads();

        // ---- PV: o[row][4tx+c] += sum_t p[row][t] * v[t][4tx+c] ----
        #pragma unroll 4
        for (int j4 = 0; j4 < 32; j4++) {
            float4 vv[4];
            #pragma unroll
            for (int jj = 0; jj < 4; jj++)
                vv[jj] = *(float4*)&v_s[(j4 * 4 + jj) * AP + tx * 4];
            #pragma unroll
            for (int i = 0; i < 8; i++) {
                float4 pv = *(float4*)&ep[(ty + 16 * i) * PP + j4 * 4];
                o_acc[i][0] += pv.x * vv[0].x + pv.y * vv[1].x + pv.z * vv[2].x + pv.w * vv[3].x;
                o_acc[i][1] += pv.x * vv[0].y + pv.y * vv[1].y + pv.z * vv[2].y + pv.w * vv[3].y;
                o_acc[i][2] += pv.x * vv[0].z + pv.y * vv[1].z + pv.z * vv[2].z + pv.w * vv[3].z;
                o_acc[i][3] += pv.x * vv[0].w + pv.y * vv[1].w + pv.z * vv[2].w + pv.w * vv[3].w;
            }
        }
    }

    // ---- epilogue: out[b][s][h*64 + d] = o / l ----
    #pragma unroll
    for (int i = 0; i < 8; i++) {
        int sg = s0 + ty + 16 * i;
        float inv = 1.f / l_r[i];
        float4 r;
        r.x = o_acc[i][0] * inv;
        r.y = o_acc[i][1] * inv;
        r.z = o_acc[i][2] * inv;
        r.w = o_acc[i][3] * inv;
        *(float4*)&out[((size_t)b * SEQ + sg) * DMODEL + h * DHEAD + tx * 4] = r;
    }
}

// ---------------------------------------------------------------------------
extern "C" void kernel_launch(void* const* d_in, const int* in_sizes, int n_in,
                              void* d_out, int out_size)
{
    const float* x  = (const float*)d_in[0];
    const float* Wq = (const float*)d_in[1];
    const float* bq = (const float*)d_in[2];
    const float* Wk = (const float*)d_in[3];
    const float* bk = (const float*)d_in[4];
    const float* Wv = (const float*)d_in[5];
    const float* bv = (const float*)d_in[6];
    const float* Er = (const float*)d_in[7];
    float* out = (float*)d_out;

    (void)in_sizes; (void)n_in; (void)out_size;

    const int smem_bytes = 43520 * 4;   // 174080
    cudaFuncSetAttribute(relattn_kernel,
                         cudaFuncAttributeMaxDynamicSharedMemorySize, smem_bytes);

    dim3 g1(DMODEL / GN, (BATCH * SEQ) / GM, 3);
    qkv_gemm_kernel<<<g1, 256>>>(x, Wq, bq, Wk, bk, Wv, bv);

    dim3 g2(SEQ / AM, BATCH * NHEAD);
    relattn_kernel<<<g2, 256, smem_bytes>>>(Er, out);
}